// round 1
// baseline (speedup 1.0000x reference)
#include <cuda_runtime.h>
#include <math.h>

#define B_ 2
#define S_ 2048
#define D_ 2048
#define H_ 16
#define HD_ 128

// Scratch (device globals: allowed; no runtime allocation)
__device__ float g_Q[B_ * H_ * S_ * HD_];   // [b][h][s][hd]
__device__ float g_K[B_ * H_ * S_ * HD_];
__device__ float g_V[B_ * H_ * S_ * HD_];
__device__ float g_AO[B_ * S_ * D_];        // [b][s][d]

// ---------------------------------------------------------------------------
// SGEMM: C[m,n] = sum_k A[m,k] * Bw[n,k]   (both K-major, i.e. X @ W^T)
// Tile 128x128, BK=8, 256 threads, 8x8 per thread, double-buffered smem.
// head_layout=1 writes C into [b][h][s][hd] (b=m>>11, s=m&2047, h=n>>7, hd=n&127)
// head_layout=0 writes plain row-major C[m*N + n].
// ---------------------------------------------------------------------------
__global__ void __launch_bounds__(256, 2)
sgemm_nt(const float* __restrict__ A, const float* __restrict__ Bw,
         float* __restrict__ C, int K, int N, int head_layout)
{
    __shared__ float As[2][8][128];
    __shared__ float Bs[2][8][128];

    const int tid = threadIdx.x;
    const int tx = tid & 15;
    const int ty = tid >> 4;
    const int bx = blockIdx.x;   // n tile
    const int by = blockIdx.y;   // m tile

    const int lrow = tid >> 1;          // 0..127
    const int lk   = (tid & 1) * 4;     // 0 or 4

    const float* Ag = A + (size_t)(by * 128 + lrow) * K + lk;
    const float* Bg = Bw + (size_t)(bx * 128 + lrow) * K + lk;

    float acc[8][8];
#pragma unroll
    for (int i = 0; i < 8; i++)
#pragma unroll
        for (int j = 0; j < 8; j++) acc[i][j] = 0.0f;

    // preload first tile
    float4 a0 = *(const float4*)Ag;
    float4 b0 = *(const float4*)Bg;
    As[0][lk + 0][lrow] = a0.x; As[0][lk + 1][lrow] = a0.y;
    As[0][lk + 2][lrow] = a0.z; As[0][lk + 3][lrow] = a0.w;
    Bs[0][lk + 0][lrow] = b0.x; Bs[0][lk + 1][lrow] = b0.y;
    Bs[0][lk + 2][lrow] = b0.z; Bs[0][lk + 3][lrow] = b0.w;
    __syncthreads();

    int buf = 0;
    for (int k0 = 8; k0 <= K; k0 += 8) {
        float4 a1, b1;
        const bool more = (k0 < K);
        if (more) {
            a1 = *(const float4*)(Ag + k0);
            b1 = *(const float4*)(Bg + k0);
        }
#pragma unroll
        for (int kk = 0; kk < 8; kk++) {
            float ar[8], br[8];
            *(float4*)&ar[0] = *(const float4*)&As[buf][kk][ty * 8];
            *(float4*)&ar[4] = *(const float4*)&As[buf][kk][ty * 8 + 4];
            *(float4*)&br[0] = *(const float4*)&Bs[buf][kk][tx * 8];
            *(float4*)&br[4] = *(const float4*)&Bs[buf][kk][tx * 8 + 4];
#pragma unroll
            for (int i = 0; i < 8; i++)
#pragma unroll
                for (int j = 0; j < 8; j++)
                    acc[i][j] += ar[i] * br[j];
        }
        if (more) {
            buf ^= 1;
            As[buf][lk + 0][lrow] = a1.x; As[buf][lk + 1][lrow] = a1.y;
            As[buf][lk + 2][lrow] = a1.z; As[buf][lk + 3][lrow] = a1.w;
            Bs[buf][lk + 0][lrow] = b1.x; Bs[buf][lk + 1][lrow] = b1.y;
            Bs[buf][lk + 2][lrow] = b1.z; Bs[buf][lk + 3][lrow] = b1.w;
            __syncthreads();
        }
    }

    // epilogue
#pragma unroll
    for (int i = 0; i < 8; i++) {
        const int m = by * 128 + ty * 8 + i;
#pragma unroll
        for (int j2 = 0; j2 < 8; j2 += 4) {
            const int n = bx * 128 + tx * 8 + j2;
            float4 ov = make_float4(acc[i][j2 + 0], acc[i][j2 + 1],
                                    acc[i][j2 + 2], acc[i][j2 + 3]);
            size_t dst;
            if (head_layout) {
                const int b = m >> 11, s = m & 2047;
                const int h = n >> 7,  hd = n & 127;
                dst = ((size_t)((b * H_ + h) * S_ + s)) * HD_ + hd;
            } else {
                dst = (size_t)m * N + n;
            }
            *(float4*)&C[dst] = ov;
        }
    }
}

// ---------------------------------------------------------------------------
// RoPE on Q and K, layout [b*h][s][hd]. Pairs (i, i+64), i<64.
// Angle computed in double so accuracy is independent of fast-math flags;
// inv_freq rounded to fp32 first to mimic the fp32 reference tables.
// ---------------------------------------------------------------------------
__global__ void rope_kernel(float* __restrict__ Q, float* __restrict__ K, int total)
{
    int idx = blockIdx.x * blockDim.x + threadIdx.x;
    if (idx >= total) return;                  // total = B*H*S*64
    const int i  = idx & 63;
    const int s  = (idx >> 6) & (S_ - 1);
    const int bh = idx >> 17;

    const float inv_freq = (float)pow(10000.0, -(double)i * (1.0 / 64.0));
    const double ang = (double)s * (double)inv_freq;
    double sd, cd;
    sincos(ang, &sd, &cd);
    const float c = (float)cd, sn = (float)sd;

    const size_t base = ((size_t)bh * S_ + s) * HD_ + i;
    float q1 = Q[base], q2 = Q[base + 64];
    Q[base]      = q1 * c - q2 * sn;
    Q[base + 64] = q1 * sn + q2 * c;
    float k1 = K[base], k2 = K[base + 64];
    K[base]      = k1 * c - k2 * sn;
    K[base + 64] = k1 * sn + k2 * c;
}

// ---------------------------------------------------------------------------
// Flash attention (fp32, causal). Block: 64 q-rows x full HD=128.
// Iterates k-tiles of 128 cols. 256 threads: tx (0..15) -> 8 cols/dims,
// ty (0..15) -> 4 rows. Online softmax, O accumulated in registers.
// smem: Qs[128][64] (d-major), Ks[128][128] (d-major), Vs[128][128] (c-major),
//       Ps[64][132] (r-major, padded).  Total ~193 KB -> 1 CTA/SM.
// ---------------------------------------------------------------------------
#define PS_STRIDE 132
#define FLASH_SMEM_FLOATS (128 * 64 + 128 * 128 + 128 * 128 + 64 * PS_STRIDE)

__global__ void __launch_bounds__(256, 1)
flash_kernel(const float* __restrict__ Q, const float* __restrict__ K,
             const float* __restrict__ V, float* __restrict__ AO)
{
    extern __shared__ float sm[];
    float* Qs = sm;                    // [128][64]
    float* Ks = Qs + 128 * 64;         // [128][128]
    float* Vs = Ks + 128 * 128;        // [128][128]
    float* Ps = Vs + 128 * 128;        // [64][PS_STRIDE]

    const int qt = blockIdx.x;
    const int h  = blockIdx.y;
    const int b  = blockIdx.z;
    const int tid = threadIdx.x;
    const int tx = tid & 15;
    const int ty = tid >> 4;
    const int r0 = ty * 4;

    const size_t bh_off = ((size_t)(b * H_ + h)) * S_ * HD_;
    const float* Qg = Q + bh_off + (size_t)qt * 64 * HD_;
    const float* Kg = K + bh_off;
    const float* Vg = V + bh_off;

    const float scale = 0.08838834764831845f;   // 1/sqrt(128)

    // Load Q tile transposed & pre-scaled: Qs[d][r]
    for (int i = tid; i < 64 * 32; i += 256) {
        int r = i & 63;
        int d = (i >> 6) << 2;
        float4 v = *(const float4*)(Qg + (size_t)r * HD_ + d);
        Qs[(d + 0) * 64 + r] = v.x * scale;
        Qs[(d + 1) * 64 + r] = v.y * scale;
        Qs[(d + 2) * 64 + r] = v.z * scale;
        Qs[(d + 3) * 64 + r] = v.w * scale;
    }

    float o[4][8];
#pragma unroll
    for (int i = 0; i < 4; i++)
#pragma unroll
        for (int j = 0; j < 8; j++) o[i][j] = 0.0f;
    float mrow[4] = {-1e30f, -1e30f, -1e30f, -1e30f};
    float lrow[4] = {0.0f, 0.0f, 0.0f, 0.0f};

    const int rowbase = qt * 64 + r0;
    const int jmax = (qt * 64 + 63) >> 7;

    __syncthreads();

    for (int j = 0; j <= jmax; j++) {
        // Load K tile transposed: Ks[d][c]
        for (int i2 = tid; i2 < 128 * 32; i2 += 256) {
            int c = i2 & 127;
            int d = (i2 >> 7) << 2;
            float4 v = *(const float4*)(Kg + ((size_t)(j * 128 + c)) * HD_ + d);
            Ks[(d + 0) * 128 + c] = v.x;
            Ks[(d + 1) * 128 + c] = v.y;
            Ks[(d + 2) * 128 + c] = v.z;
            Ks[(d + 3) * 128 + c] = v.w;
        }
        // Load V tile straight: Vs[c][d]
        for (int i2 = tid; i2 < 128 * 32; i2 += 256) {
            float4 v = *(const float4*)(Vg + (size_t)j * 128 * HD_ + i2 * 4);
            *(float4*)(Vs + i2 * 4) = v;
        }
        __syncthreads();

        // S = Q K^T (scaled), per-thread 4x8
        float sacc[4][8];
#pragma unroll
        for (int i = 0; i < 4; i++)
#pragma unroll
            for (int jj = 0; jj < 8; jj++) sacc[i][jj] = 0.0f;

#pragma unroll 8
        for (int d = 0; d < 128; d++) {
            float4 qv  = *(const float4*)(Qs + d * 64 + r0);
            float4 kv0 = *(const float4*)(Ks + d * 128 + tx * 8);
            float4 kv1 = *(const float4*)(Ks + d * 128 + tx * 8 + 4);
            const float qa[4] = {qv.x, qv.y, qv.z, qv.w};
            const float ka[8] = {kv0.x, kv0.y, kv0.z, kv0.w,
                                 kv1.x, kv1.y, kv1.z, kv1.w};
#pragma unroll
            for (int i = 0; i < 4; i++)
#pragma unroll
                for (int jj = 0; jj < 8; jj++)
                    sacc[i][jj] += qa[i] * ka[jj];
        }

        // causal mask + online softmax
        const int cbase = j * 128 + tx * 8;
#pragma unroll
        for (int i = 0; i < 4; i++) {
            const int rg = rowbase + i;
            float tmax = -1e30f;
#pragma unroll
            for (int jj = 0; jj < 8; jj++) {
                float sv = (cbase + jj <= rg) ? sacc[i][jj] : -1e30f;
                sacc[i][jj] = sv;
                tmax = fmaxf(tmax, sv);
            }
            tmax = fmaxf(tmax, __shfl_xor_sync(0xffffffffu, tmax, 1));
            tmax = fmaxf(tmax, __shfl_xor_sync(0xffffffffu, tmax, 2));
            tmax = fmaxf(tmax, __shfl_xor_sync(0xffffffffu, tmax, 4));
            tmax = fmaxf(tmax, __shfl_xor_sync(0xffffffffu, tmax, 8));

            const float mnew  = fmaxf(mrow[i], tmax);
            const float alpha = __expf(mrow[i] - mnew);
            mrow[i] = mnew;

            float rsum = 0.0f;
#pragma unroll
            for (int jj = 0; jj < 8; jj++) {
                float p = __expf(sacc[i][jj] - mnew);
                sacc[i][jj] = p;
                rsum += p;
            }
            rsum += __shfl_xor_sync(0xffffffffu, rsum, 1);
            rsum += __shfl_xor_sync(0xffffffffu, rsum, 2);
            rsum += __shfl_xor_sync(0xffffffffu, rsum, 4);
            rsum += __shfl_xor_sync(0xffffffffu, rsum, 8);

            lrow[i] = lrow[i] * alpha + rsum;
#pragma unroll
            for (int jd = 0; jd < 8; jd++) o[i][jd] *= alpha;

            // store P row-major
            *(float4*)(Ps + (r0 + i) * PS_STRIDE + tx * 8) =
                make_float4(sacc[i][0], sacc[i][1], sacc[i][2], sacc[i][3]);
            *(float4*)(Ps + (r0 + i) * PS_STRIDE + tx * 8 + 4) =
                make_float4(sacc[i][4], sacc[i][5], sacc[i][6], sacc[i][7]);
        }
        __syncthreads();

        // O += P V, per-thread 4 rows x 8 dims
#pragma unroll 4
        for (int c = 0; c < 128; c++) {
            float pv[4];
#pragma unroll
            for (int i = 0; i < 4; i++)
                pv[i] = Ps[(r0 + i) * PS_STRIDE + c];
            float4 v0 = *(const float4*)(Vs + c * 128 + tx * 8);
            float4 v1 = *(const float4*)(Vs + c * 128 + tx * 8 + 4);
            const float va[8] = {v0.x, v0.y, v0.z, v0.w, v1.x, v1.y, v1.z, v1.w};
#pragma unroll
            for (int i = 0; i < 4; i++)
#pragma unroll
                for (int jd = 0; jd < 8; jd++)
                    o[i][jd] += pv[i] * va[jd];
        }
        __syncthreads();
    }

    // epilogue: divide by l, write to AO[b][s][h*128 + d]
#pragma unroll
    for (int i = 0; i < 4; i++) {
        const float inv_l = 1.0f / lrow[i];
        const int s = rowbase + i;
        const size_t dst = ((size_t)(b * S_ + s)) * D_ + h * HD_ + tx * 8;
        *(float4*)(g_AO + 0, (void)0, &AO[dst]) = make_float4(
            o[i][0] * inv_l, o[i][1] * inv_l, o[i][2] * inv_l, o[i][3] * inv_l);
        *(float4*)&AO[dst + 4] = make_float4(
            o[i][4] * inv_l, o[i][5] * inv_l, o[i][6] * inv_l, o[i][7] * inv_l);
    }
}

// ---------------------------------------------------------------------------
extern "C" void kernel_launch(void* const* d_in, const int* in_sizes, int n_in,
                              void* d_out, int out_size)
{
    (void)in_sizes; (void)n_in; (void)out_size;
    const float* x  = (const float*)d_in[0];
    // d_in[1] = mask (tril -> causal, handled analytically)
    const float* Wq = (const float*)d_in[2];
    const float* Wk = (const float*)d_in[3];
    const float* Wv = (const float*)d_in[4];
    const float* Wo = (const float*)d_in[5];
    float* out = (float*)d_out;

    float *q, *k, *v, *ao;
    cudaGetSymbolAddress((void**)&q,  g_Q);
    cudaGetSymbolAddress((void**)&k,  g_K);
    cudaGetSymbolAddress((void**)&v,  g_V);
    cudaGetSymbolAddress((void**)&ao, g_AO);

    const int flash_smem = FLASH_SMEM_FLOATS * sizeof(float);
    cudaFuncSetAttribute(flash_kernel,
                         cudaFuncAttributeMaxDynamicSharedMemorySize, flash_smem);

    dim3 ggrid(D_ / 128, (B_ * S_) / 128);   // (16, 32)
    sgemm_nt<<<ggrid, 256>>>(x, Wq, q, D_, D_, 1);
    sgemm_nt<<<ggrid, 256>>>(x, Wk, k, D_, D_, 1);
    sgemm_nt<<<ggrid, 256>>>(x, Wv, v, D_, D_, 1);

    const int rope_total = B_ * H_ * S_ * 64;
    rope_kernel<<<(rope_total + 255) / 256, 256>>>(q, k, rope_total);

    flash_kernel<<<dim3(S_ / 64, H_, B_), 256, flash_smem>>>(q, k, v, ao);

    sgemm_nt<<<ggrid, 256>>>(ao, Wo, out, D_, D_, 0);
}

// round 3
// speedup vs baseline: 2.1949x; 2.1949x over previous
#include <cuda_runtime.h>
#include <cuda_bf16.h>
#include <math.h>
#include <stdint.h>

#define B_ 2
#define S_ 2048
#define D_ 2048
#define H_ 16
#define HD_ 128

// ---------------- device scratch (no runtime allocation) ----------------
__device__ float g_Q[B_ * H_ * S_ * HD_];   // [b][h][s][hd]
__device__ float g_K[B_ * H_ * S_ * HD_];
__device__ float g_V[B_ * H_ * S_ * HD_];
__device__ float g_AO[B_ * S_ * D_];        // [b][s][d]

__device__ __nv_bfloat16 g_xhi[B_ * S_ * D_];
__device__ __nv_bfloat16 g_xlo[B_ * S_ * D_];
__device__ __nv_bfloat16 g_wqhi[D_ * D_], g_wqlo[D_ * D_];
__device__ __nv_bfloat16 g_wkhi[D_ * D_], g_wklo[D_ * D_];
__device__ __nv_bfloat16 g_wvhi[D_ * D_], g_wvlo[D_ * D_];
__device__ __nv_bfloat16 g_wohi[D_ * D_], g_wolo[D_ * D_];
__device__ __nv_bfloat16 g_aohi[B_ * S_ * D_];
__device__ __nv_bfloat16 g_aolo[B_ * S_ * D_];

__device__ float g_cos[S_ * 64];
__device__ float g_sin[S_ * 64];

// ---------------- helpers ----------------
__device__ __forceinline__ uint32_t smem_u32(const void* p) {
    uint32_t a;
    asm("{ .reg .u64 t; cvta.to.shared.u64 t, %1; cvt.u32.u64 %0, t; }"
        : "=r"(a) : "l"(p));
    return a;
}
static __device__ __forceinline__ uint32_t swz128(uint32_t o) {
    return o ^ ((o >> 3) & 0x70);
}
__device__ __forceinline__ void cp16(uint32_t saddr, const void* gptr) {
    asm volatile("cp.async.cg.shared.global [%0], [%1], 16;"
                 :: "r"(saddr), "l"(gptr) : "memory");
}
#define CP_COMMIT() asm volatile("cp.async.commit_group;" ::: "memory")

__device__ __forceinline__ void ldsm_x4(uint32_t a, uint32_t& r0, uint32_t& r1,
                                        uint32_t& r2, uint32_t& r3) {
    asm volatile("ldmatrix.sync.aligned.m8n8.x4.shared.b16 {%0,%1,%2,%3}, [%4];"
                 : "=r"(r0), "=r"(r1), "=r"(r2), "=r"(r3) : "r"(a));
}
__device__ __forceinline__ void ldsm_x2(uint32_t a, uint32_t& r0, uint32_t& r1) {
    asm volatile("ldmatrix.sync.aligned.m8n8.x2.shared.b16 {%0,%1}, [%2];"
                 : "=r"(r0), "=r"(r1) : "r"(a));
}
__device__ __forceinline__ void mma16816(float* d, const uint32_t* a, const uint32_t* b) {
    asm volatile(
        "mma.sync.aligned.m16n8k16.row.col.f32.bf16.bf16.f32 "
        "{%0,%1,%2,%3}, {%4,%5,%6,%7}, {%8,%9}, {%0,%1,%2,%3};"
        : "+f"(d[0]), "+f"(d[1]), "+f"(d[2]), "+f"(d[3])
        : "r"(a[0]), "r"(a[1]), "r"(a[2]), "r"(a[3]), "r"(b[0]), "r"(b[1]));
}

// ---------------------------------------------------------------------------
// Split fp32 -> bf16 hi/lo (Markidis). Vectorized by 4.
// ---------------------------------------------------------------------------
__global__ void split_bf16(const float* __restrict__ in,
                           __nv_bfloat16* __restrict__ hi,
                           __nv_bfloat16* __restrict__ lo, int n4)
{
    int i = blockIdx.x * blockDim.x + threadIdx.x;
    if (i >= n4) return;
    float4 v = ((const float4*)in)[i];
    __nv_bfloat16 h0 = __float2bfloat16(v.x);
    __nv_bfloat16 h1 = __float2bfloat16(v.y);
    __nv_bfloat16 h2 = __float2bfloat16(v.z);
    __nv_bfloat16 h3 = __float2bfloat16(v.w);
    __nv_bfloat16 l0 = __float2bfloat16(v.x - __bfloat162float(h0));
    __nv_bfloat16 l1 = __float2bfloat16(v.y - __bfloat162float(h1));
    __nv_bfloat16 l2 = __float2bfloat16(v.z - __bfloat162float(h2));
    __nv_bfloat16 l3 = __float2bfloat16(v.w - __bfloat162float(h3));
    __nv_bfloat162* hi2 = (__nv_bfloat162*)hi;
    __nv_bfloat162* lo2 = (__nv_bfloat162*)lo;
    hi2[2 * i]     = __nv_bfloat162(h0, h1);
    hi2[2 * i + 1] = __nv_bfloat162(h2, h3);
    lo2[2 * i]     = __nv_bfloat162(l0, l1);
    lo2[2 * i + 1] = __nv_bfloat162(l2, l3);
}

// ---------------------------------------------------------------------------
// mma.sync split-bf16 SGEMM: C[m,n] = sum_k A[m,k]*B[n,k] (fp32-accurate).
// Block tile 128x128, BK=64 (128B rows, SW128 swizzle), 8 warps in 2x4,
// warp tile 64x32, cp.async double-buffered pipeline.
// head_layout=1: C -> [b][h][s][hd]; else row-major [m][n].
// ---------------------------------------------------------------------------
#define TCT16 16384u                    // bytes per smem tile (128 x 128B)
#define TC_SMEM_BYTES (2u * 4u * TCT16) // 2 bufs x 4 tiles = 128 KB

__global__ void __launch_bounds__(256, 1)
sgemm_tc(const __nv_bfloat16* __restrict__ Ahi, const __nv_bfloat16* __restrict__ Alo,
         const __nv_bfloat16* __restrict__ Bhi, const __nv_bfloat16* __restrict__ Blo,
         float* __restrict__ C, int head_layout)
{
    extern __shared__ char smem[];
    const uint32_t sbase = smem_u32(smem);

    const int tid  = threadIdx.x;
    const int lane = tid & 31;
    const int w    = tid >> 5;
    const int wm   = w >> 2;          // 0..1
    const int wn   = w & 3;           // 0..3
    const int m0w  = wm * 64;
    const int n0w  = wn * 32;

    const int bx = blockIdx.x;        // n tile
    const int by = blockIdx.y;        // m tile
    const int m0 = by * 128;
    const int n0 = bx * 128;

    // per-thread load slots: u = tid + t*256, row = u>>3, col16 = u&7
    uint32_t swofs[4];
    const float* dummy;
    (void)dummy;
#pragma unroll
    for (int t = 0; t < 4; t++) {
        const int u = tid + (t << 8);
        swofs[t] = swz128((uint32_t)((u >> 3) * 128 + (u & 7) * 16));
    }

    float acc[4][4][4];
#pragma unroll
    for (int i = 0; i < 4; i++)
#pragma unroll
        for (int j = 0; j < 4; j++)
#pragma unroll
            for (int r = 0; r < 4; r++) acc[i][j][r] = 0.0f;

    // fragment smem addresses (constant across chunks except kk/buffer offset)
    const uint32_t arow = (uint32_t)(m0w + (lane & 15));       // + mt*16
    const uint32_t acol = (uint32_t)((lane >> 4) << 4);        // + kk*32
    const uint32_t brow = (uint32_t)(n0w + (lane & 7));        // + nt*8
    const uint32_t bcol = (uint32_t)(((lane >> 3) & 1) << 4);  // + kk*32

#define LOAD_CHUNK(c, buf)                                                     \
    {                                                                          \
        const uint32_t bofs = sbase + (uint32_t)(buf) * (4u * TCT16);          \
        const int k0 = (c) * 64;                                               \
        _Pragma("unroll")                                                      \
        for (int t = 0; t < 4; t++) {                                          \
            const int u = tid + (t << 8);                                      \
            const int r = u >> 3;                                              \
            const int c16 = u & 7;                                             \
            const size_t ga = (size_t)(m0 + r) * D_ + k0 + c16 * 8;            \
            const size_t gb = (size_t)(n0 + r) * D_ + k0 + c16 * 8;            \
            cp16(bofs + 0u * TCT16 + swofs[t], Ahi + ga);                      \
            cp16(bofs + 1u * TCT16 + swofs[t], Alo + ga);                      \
            cp16(bofs + 2u * TCT16 + swofs[t], Bhi + gb);                      \
            cp16(bofs + 3u * TCT16 + swofs[t], Blo + gb);                      \
        }                                                                      \
        CP_COMMIT();                                                           \
    }

    LOAD_CHUNK(0, 0);

    for (int c = 0; c < 32; c++) {
        if (c < 31) {
            LOAD_CHUNK(c + 1, (c + 1) & 1);
            asm volatile("cp.async.wait_group 1;" ::: "memory");
        } else {
            asm volatile("cp.async.wait_group 0;" ::: "memory");
        }
        __syncthreads();

        const uint32_t bofs = sbase + (uint32_t)(c & 1) * (4u * TCT16);
        const uint32_t Abase_hi = bofs + 0u * TCT16;
        const uint32_t Abase_lo = bofs + 1u * TCT16;
        const uint32_t Bbase_hi = bofs + 2u * TCT16;
        const uint32_t Bbase_lo = bofs + 3u * TCT16;

#pragma unroll
        for (int kk = 0; kk < 4; kk++) {
            uint32_t ah[4][4], al[4][4], bh[4][2], bl[4][2];
            const uint32_t kb = (uint32_t)(kk * 32);
#pragma unroll
            for (int mt = 0; mt < 4; mt++) {
                const uint32_t ofs =
                    swz128((arow + mt * 16u) * 128u + acol + kb);
                ldsm_x4(Abase_hi + ofs, ah[mt][0], ah[mt][1], ah[mt][2], ah[mt][3]);
                ldsm_x4(Abase_lo + ofs, al[mt][0], al[mt][1], al[mt][2], al[mt][3]);
            }
#pragma unroll
            for (int nt = 0; nt < 4; nt++) {
                const uint32_t ofs =
                    swz128((brow + nt * 8u) * 128u + bcol + kb);
                ldsm_x2(Bbase_hi + ofs, bh[nt][0], bh[nt][1]);
                ldsm_x2(Bbase_lo + ofs, bl[nt][0], bl[nt][1]);
            }
#pragma unroll
            for (int mt = 0; mt < 4; mt++)
#pragma unroll
                for (int nt = 0; nt < 4; nt++) {
                    mma16816(acc[mt][nt], ah[mt], bh[nt]);
                    mma16816(acc[mt][nt], ah[mt], bl[nt]);
                    mma16816(acc[mt][nt], al[mt], bh[nt]);
                }
        }
        __syncthreads();
    }

    // epilogue: acc[mt][nt][{r0c0,r0c1,r1c0,r1c1}]
    const int lr = lane >> 2;          // 0..7
    const int lc = (lane & 3) * 2;     // 0,2,4,6
#pragma unroll
    for (int mt = 0; mt < 4; mt++) {
#pragma unroll
        for (int rr = 0; rr < 2; rr++) {
            const int m = m0 + m0w + mt * 16 + rr * 8 + lr;
            size_t dstbase;
            if (head_layout) {
                const int bb = m >> 11, s = m & (S_ - 1);
                // n = n0 + n0w + ... ; h = n>>7, hd = n&127
                dstbase = 0;  // computed per store below
                const size_t rowoff = ((size_t)(bb * H_) * S_ + s) * HD_;
#pragma unroll
                for (int nt = 0; nt < 4; nt++) {
                    const int n = n0 + n0w + nt * 8 + lc;
                    const int h = n >> 7, hd = n & 127;
                    float2 v = rr == 0
                        ? make_float2(acc[mt][nt][0], acc[mt][nt][1])
                        : make_float2(acc[mt][nt][2], acc[mt][nt][3]);
                    *(float2*)&C[rowoff + (size_t)h * S_ * HD_ + hd] = v;
                }
            } else {
                dstbase = (size_t)m * D_;
#pragma unroll
                for (int nt = 0; nt < 4; nt++) {
                    const int n = n0 + n0w + nt * 8 + lc;
                    float2 v = rr == 0
                        ? make_float2(acc[mt][nt][0], acc[mt][nt][1])
                        : make_float2(acc[mt][nt][2], acc[mt][nt][3]);
                    *(float2*)&C[dstbase + n] = v;
                }
            }
        }
    }
}

// ---------------------------------------------------------------------------
// RoPE tables (double math, 131K threads once) + cheap apply kernel
// ---------------------------------------------------------------------------
__global__ void rope_table_kernel()
{
    int idx = blockIdx.x * blockDim.x + threadIdx.x;
    if (idx >= S_ * 64) return;
    const int i = idx & 63;
    const int s = idx >> 6;
    const float inv_freq = (float)pow(10000.0, -(double)i * (1.0 / 64.0));
    const double ang = (double)s * (double)inv_freq;
    double sd, cd;
    sincos(ang, &sd, &cd);
    g_cos[idx] = (float)cd;
    g_sin[idx] = (float)sd;
}

__global__ void rope_kernel(float* __restrict__ Q, float* __restrict__ K, int total)
{
    int idx = blockIdx.x * blockDim.x + threadIdx.x;
    if (idx >= total) return;                  // total = B*H*S*64
    const int i  = idx & 63;
    const int s  = (idx >> 6) & (S_ - 1);
    const int bh = idx >> 17;

    const int ti = (s << 6) + i;
    const float c  = g_cos[ti];
    const float sn = g_sin[ti];

    const size_t base = ((size_t)bh * S_ + s) * HD_ + i;
    float q1 = Q[base], q2 = Q[base + 64];
    Q[base]      = q1 * c - q2 * sn;
    Q[base + 64] = q1 * sn + q2 * c;
    float k1 = K[base], k2 = K[base + 64];
    K[base]      = k1 * c - k2 * sn;
    K[base + 64] = k1 * sn + k2 * c;
}

// ---------------------------------------------------------------------------
// Flash attention (fp32, causal) — unchanged from R1 (passed).
// ---------------------------------------------------------------------------
#define PS_STRIDE 132
#define FLASH_SMEM_FLOATS (128 * 64 + 128 * 128 + 128 * 128 + 64 * PS_STRIDE)

__global__ void __launch_bounds__(256, 1)
flash_kernel(const float* __restrict__ Q, const float* __restrict__ K,
             const float* __restrict__ V, float* __restrict__ AO)
{
    extern __shared__ float sm[];
    float* Qs = sm;                    // [128][64]
    float* Ks = Qs + 128 * 64;         // [128][128]
    float* Vs = Ks + 128 * 128;        // [128][128]
    float* Ps = Vs + 128 * 128;        // [64][PS_STRIDE]

    const int qt = blockIdx.x;
    const int h  = blockIdx.y;
    const int b  = blockIdx.z;
    const int tid = threadIdx.x;
    const int tx = tid & 15;
    const int ty = tid >> 4;
    const int r0 = ty * 4;

    const size_t bh_off = ((size_t)(b * H_ + h)) * S_ * HD_;
    const float* Qg = Q + bh_off + (size_t)qt * 64 * HD_;
    const float* Kg = K + bh_off;
    const float* Vg = V + bh_off;

    const float scale = 0.08838834764831845f;   // 1/sqrt(128)

    for (int i = tid; i < 64 * 32; i += 256) {
        int r = i & 63;
        int d = (i >> 6) << 2;
        float4 v = *(const float4*)(Qg + (size_t)r * HD_ + d);
        Qs[(d + 0) * 64 + r] = v.x * scale;
        Qs[(d + 1) * 64 + r] = v.y * scale;
        Qs[(d + 2) * 64 + r] = v.z * scale;
        Qs[(d + 3) * 64 + r] = v.w * scale;
    }

    float o[4][8];
#pragma unroll
    for (int i = 0; i < 4; i++)
#pragma unroll
        for (int j = 0; j < 8; j++) o[i][j] = 0.0f;
    float mrow[4] = {-1e30f, -1e30f, -1e30f, -1e30f};
    float lrow[4] = {0.0f, 0.0f, 0.0f, 0.0f};

    const int rowbase = qt * 64 + r0;
    const int jmax = (qt * 64 + 63) >> 7;

    __syncthreads();

    for (int j = 0; j <= jmax; j++) {
        for (int i2 = tid; i2 < 128 * 32; i2 += 256) {
            int c = i2 & 127;
            int d = (i2 >> 7) << 2;
            float4 v = *(const float4*)(Kg + ((size_t)(j * 128 + c)) * HD_ + d);
            Ks[(d + 0) * 128 + c] = v.x;
            Ks[(d + 1) * 128 + c] = v.y;
            Ks[(d + 2) * 128 + c] = v.z;
            Ks[(d + 3) * 128 + c] = v.w;
        }
        for (int i2 = tid; i2 < 128 * 32; i2 += 256) {
            float4 v = *(const float4*)(Vg + (size_t)j * 128 * HD_ + i2 * 4);
            *(float4*)(Vs + i2 * 4) = v;
        }
        __syncthreads();

        float sacc[4][8];
#pragma unroll
        for (int i = 0; i < 4; i++)
#pragma unroll
            for (int jj = 0; jj < 8; jj++) sacc[i][jj] = 0.0f;

#pragma unroll 8
        for (int d = 0; d < 128; d++) {
            float4 qv  = *(const float4*)(Qs + d * 64 + r0);
            float4 kv0 = *(const float4*)(Ks + d * 128 + tx * 8);
            float4 kv1 = *(const float4*)(Ks + d * 128 + tx * 8 + 4);
            const float qa[4] = {qv.x, qv.y, qv.z, qv.w};
            const float ka[8] = {kv0.x, kv0.y, kv0.z, kv0.w,
                                 kv1.x, kv1.y, kv1.z, kv1.w};
#pragma unroll
            for (int i = 0; i < 4; i++)
#pragma unroll
                for (int jj = 0; jj < 8; jj++)
                    sacc[i][jj] += qa[i] * ka[jj];
        }

        const int cbase = j * 128 + tx * 8;
#pragma unroll
        for (int i = 0; i < 4; i++) {
            const int rg = rowbase + i;
            float tmax = -1e30f;
#pragma unroll
            for (int jj = 0; jj < 8; jj++) {
                float sv = (cbase + jj <= rg) ? sacc[i][jj] : -1e30f;
                sacc[i][jj] = sv;
                tmax = fmaxf(tmax, sv);
            }
            tmax = fmaxf(tmax, __shfl_xor_sync(0xffffffffu, tmax, 1));
            tmax = fmaxf(tmax, __shfl_xor_sync(0xffffffffu, tmax, 2));
            tmax = fmaxf(tmax, __shfl_xor_sync(0xffffffffu, tmax, 4));
            tmax = fmaxf(tmax, __shfl_xor_sync(0xffffffffu, tmax, 8));

            const float mnew  = fmaxf(mrow[i], tmax);
            const float alpha = __expf(mrow[i] - mnew);
            mrow[i] = mnew;

            float rsum = 0.0f;
#pragma unroll
            for (int jj = 0; jj < 8; jj++) {
                float p = __expf(sacc[i][jj] - mnew);
                sacc[i][jj] = p;
                rsum += p;
            }
            rsum += __shfl_xor_sync(0xffffffffu, rsum, 1);
            rsum += __shfl_xor_sync(0xffffffffu, rsum, 2);
            rsum += __shfl_xor_sync(0xffffffffu, rsum, 4);
            rsum += __shfl_xor_sync(0xffffffffu, rsum, 8);

            lrow[i] = lrow[i] * alpha + rsum;
#pragma unroll
            for (int jd = 0; jd < 8; jd++) o[i][jd] *= alpha;

            *(float4*)(Ps + (r0 + i) * PS_STRIDE + tx * 8) =
                make_float4(sacc[i][0], sacc[i][1], sacc[i][2], sacc[i][3]);
            *(float4*)(Ps + (r0 + i) * PS_STRIDE + tx * 8 + 4) =
                make_float4(sacc[i][4], sacc[i][5], sacc[i][6], sacc[i][7]);
        }
        __syncthreads();

#pragma unroll 4
        for (int c = 0; c < 128; c++) {
            float pv[4];
#pragma unroll
            for (int i = 0; i < 4; i++)
                pv[i] = Ps[(r0 + i) * PS_STRIDE + c];
            float4 v0 = *(const float4*)(Vs + c * 128 + tx * 8);
            float4 v1 = *(const float4*)(Vs + c * 128 + tx * 8 + 4);
            const float va[8] = {v0.x, v0.y, v0.z, v0.w, v1.x, v1.y, v1.z, v1.w};
#pragma unroll
            for (int i = 0; i < 4; i++)
#pragma unroll
                for (int jd = 0; jd < 8; jd++)
                    o[i][jd] += pv[i] * va[jd];
        }
        __syncthreads();
    }

#pragma unroll
    for (int i = 0; i < 4; i++) {
        const float inv_l = 1.0f / lrow[i];
        const int s = rowbase + i;
        const size_t dst = ((size_t)(b * S_ + s)) * D_ + h * HD_ + tx * 8;
        *(float4*)&AO[dst] = make_float4(
            o[i][0] * inv_l, o[i][1] * inv_l, o[i][2] * inv_l, o[i][3] * inv_l);
        *(float4*)&AO[dst + 4] = make_float4(
            o[i][4] * inv_l, o[i][5] * inv_l, o[i][6] * inv_l, o[i][7] * inv_l);
    }
}

// ---------------------------------------------------------------------------
extern "C" void kernel_launch(void* const* d_in, const int* in_sizes, int n_in,
                              void* d_out, int out_size)
{
    (void)in_sizes; (void)n_in; (void)out_size;
    const float* x  = (const float*)d_in[0];
    // d_in[1] = mask (tril -> causal, handled analytically)
    const float* Wq = (const float*)d_in[2];
    const float* Wk = (const float*)d_in[3];
    const float* Wv = (const float*)d_in[4];
    const float* Wo = (const float*)d_in[5];
    float* out = (float*)d_out;

    float *q, *k, *v, *ao;
    cudaGetSymbolAddress((void**)&q,  g_Q);
    cudaGetSymbolAddress((void**)&k,  g_K);
    cudaGetSymbolAddress((void**)&v,  g_V);
    cudaGetSymbolAddress((void**)&ao, g_AO);

    __nv_bfloat16 *xhi, *xlo, *aohi, *aolo;
    __nv_bfloat16 *wqhi, *wqlo, *wkhi, *wklo, *wvhi, *wvlo, *wohi, *wolo;
    cudaGetSymbolAddress((void**)&xhi, g_xhi);
    cudaGetSymbolAddress((void**)&xlo, g_xlo);
    cudaGetSymbolAddress((void**)&aohi, g_aohi);
    cudaGetSymbolAddress((void**)&aolo, g_aolo);
    cudaGetSymbolAddress((void**)&wqhi, g_wqhi);
    cudaGetSymbolAddress((void**)&wqlo, g_wqlo);
    cudaGetSymbolAddress((void**)&wkhi, g_wkhi);
    cudaGetSymbolAddress((void**)&wklo, g_wklo);
    cudaGetSymbolAddress((void**)&wvhi, g_wvhi);
    cudaGetSymbolAddress((void**)&wvlo, g_wvlo);
    cudaGetSymbolAddress((void**)&wohi, g_wohi);
    cudaGetSymbolAddress((void**)&wolo, g_wolo);

    const int flash_smem = FLASH_SMEM_FLOATS * sizeof(float);
    cudaFuncSetAttribute(flash_kernel,
                         cudaFuncAttributeMaxDynamicSharedMemorySize, flash_smem);
    cudaFuncSetAttribute(sgemm_tc,
                         cudaFuncAttributeMaxDynamicSharedMemorySize, TC_SMEM_BYTES);

    // 1) splits
    const int xn4 = (B_ * S_ * D_) / 4;
    const int wn4 = (D_ * D_) / 4;
    split_bf16<<<(xn4 + 255) / 256, 256>>>(x, xhi, xlo, xn4);
    split_bf16<<<(wn4 + 255) / 256, 256>>>(Wq, wqhi, wqlo, wn4);
    split_bf16<<<(wn4 + 255) / 256, 256>>>(Wk, wkhi, wklo, wn4);
    split_bf16<<<(wn4 + 255) / 256, 256>>>(Wv, wvhi, wvlo, wn4);
    split_bf16<<<(wn4 + 255) / 256, 256>>>(Wo, wohi, wolo, wn4);

    // 2) rope tables
    rope_table_kernel<<<(S_ * 64 + 255) / 256, 256>>>();

    // 3) projections on tensor cores (mma.sync bf16 split)
    dim3 ggrid(D_ / 128, (B_ * S_) / 128);   // (16, 32)
    sgemm_tc<<<ggrid, 256, TC_SMEM_BYTES>>>(xhi, xlo, wqhi, wqlo, q, 1);
    sgemm_tc<<<ggrid, 256, TC_SMEM_BYTES>>>(xhi, xlo, wkhi, wklo, k, 1);
    sgemm_tc<<<ggrid, 256, TC_SMEM_BYTES>>>(xhi, xlo, wvhi, wvlo, v, 1);

    // 4) rope
    const int rope_total = B_ * H_ * S_ * 64;
    rope_kernel<<<(rope_total + 255) / 256, 256>>>(q, k, rope_total);

    // 5) attention
    flash_kernel<<<dim3(S_ / 64, H_, B_), 256, flash_smem>>>(q, k, v, ao);

    // 6) output projection
    split_bf16<<<(xn4 + 255) / 256, 256>>>(ao, aohi, aolo, xn4);
    sgemm_tc<<<ggrid, 256, TC_SMEM_BYTES>>>(aohi, aolo, wohi, wolo, out, 0);
}

// round 4
// speedup vs baseline: 4.0307x; 1.8364x over previous
#include <cuda_runtime.h>
#include <cuda_bf16.h>
#include <math.h>
#include <stdint.h>

#define B_ 2
#define S_ 2048
#define D_ 2048
#define H_ 16
#define HD_ 128

// ---------------- device scratch (no runtime allocation) ----------------
__device__ float g_Q[B_ * H_ * S_ * HD_];   // [b][h][s][hd] fp32 (pre-rope)
__device__ float g_K[B_ * H_ * S_ * HD_];
__device__ float g_V[B_ * H_ * S_ * HD_];
__device__ float g_AO[B_ * S_ * D_];        // [b][s][d]

__device__ __nv_bfloat16 g_xhi[B_ * S_ * D_];
__device__ __nv_bfloat16 g_xlo[B_ * S_ * D_];
__device__ __nv_bfloat16 g_wqhi[D_ * D_], g_wqlo[D_ * D_];
__device__ __nv_bfloat16 g_wkhi[D_ * D_], g_wklo[D_ * D_];
__device__ __nv_bfloat16 g_wvhi[D_ * D_], g_wvlo[D_ * D_];
__device__ __nv_bfloat16 g_wohi[D_ * D_], g_wolo[D_ * D_];
__device__ __nv_bfloat16 g_aohi[B_ * S_ * D_];
__device__ __nv_bfloat16 g_aolo[B_ * S_ * D_];

// attention operands (bf16 hi/lo, head layout)
__device__ __nv_bfloat16 g_qh[B_ * H_ * S_ * HD_], g_ql[B_ * H_ * S_ * HD_];
__device__ __nv_bfloat16 g_kh[B_ * H_ * S_ * HD_], g_kl[B_ * H_ * S_ * HD_];
__device__ __nv_bfloat16 g_vh[B_ * H_ * S_ * HD_], g_vl[B_ * H_ * S_ * HD_];

__device__ float g_cos[S_ * 64];
__device__ float g_sin[S_ * 64];

// ---------------- helpers ----------------
__device__ __forceinline__ uint32_t smem_u32(const void* p) {
    uint32_t a;
    asm("{ .reg .u64 t; cvta.to.shared.u64 t, %1; cvt.u32.u64 %0, t; }"
        : "=r"(a) : "l"(p));
    return a;
}
static __device__ __forceinline__ uint32_t swz128(uint32_t o) {
    return o ^ ((o >> 3) & 0x70);
}
// swizzle for 256B rows (flash tiles): row-major, 16B chunk xor by row&7
static __device__ __forceinline__ uint32_t swzf(uint32_t row, uint32_t colbyte) {
    return row * 256u + (colbyte ^ ((row & 7u) << 4));
}
__device__ __forceinline__ void cp16(uint32_t saddr, const void* gptr) {
    asm volatile("cp.async.cg.shared.global [%0], [%1], 16;"
                 :: "r"(saddr), "l"(gptr) : "memory");
}
#define CP_COMMIT() asm volatile("cp.async.commit_group;" ::: "memory")

__device__ __forceinline__ void ldsm_x4(uint32_t a, uint32_t* r) {
    asm volatile("ldmatrix.sync.aligned.m8n8.x4.shared.b16 {%0,%1,%2,%3}, [%4];"
                 : "=r"(r[0]), "=r"(r[1]), "=r"(r[2]), "=r"(r[3]) : "r"(a));
}
__device__ __forceinline__ void ldsm_x2(uint32_t a, uint32_t* r) {
    asm volatile("ldmatrix.sync.aligned.m8n8.x2.shared.b16 {%0,%1}, [%2];"
                 : "=r"(r[0]), "=r"(r[1]) : "r"(a));
}
__device__ __forceinline__ void ldsm_x2t(uint32_t a, uint32_t* r) {
    asm volatile("ldmatrix.sync.aligned.m8n8.x2.trans.shared.b16 {%0,%1}, [%2];"
                 : "=r"(r[0]), "=r"(r[1]) : "r"(a));
}
__device__ __forceinline__ void mma16816(float* d, const uint32_t* a, const uint32_t* b) {
    asm volatile(
        "mma.sync.aligned.m16n8k16.row.col.f32.bf16.bf16.f32 "
        "{%0,%1,%2,%3}, {%4,%5,%6,%7}, {%8,%9}, {%0,%1,%2,%3};"
        : "+f"(d[0]), "+f"(d[1]), "+f"(d[2]), "+f"(d[3])
        : "r"(a[0]), "r"(a[1]), "r"(a[2]), "r"(a[3]), "r"(b[0]), "r"(b[1]));
}
__device__ __forceinline__ uint32_t pack2(__nv_bfloat16 a, __nv_bfloat16 b) {
    __nv_bfloat162 t(a, b);   // low = a
    return *(uint32_t*)&t;
}

// ---------------------------------------------------------------------------
// Split fp32 -> bf16 hi/lo (Markidis). Vectorized by 4.
// ---------------------------------------------------------------------------
__global__ void split_bf16(const float* __restrict__ in,
                           __nv_bfloat16* __restrict__ hi,
                           __nv_bfloat16* __restrict__ lo, int n4)
{
    int i = blockIdx.x * blockDim.x + threadIdx.x;
    if (i >= n4) return;
    float4 v = ((const float4*)in)[i];
    __nv_bfloat16 h0 = __float2bfloat16(v.x);
    __nv_bfloat16 h1 = __float2bfloat16(v.y);
    __nv_bfloat16 h2 = __float2bfloat16(v.z);
    __nv_bfloat16 h3 = __float2bfloat16(v.w);
    __nv_bfloat16 l0 = __float2bfloat16(v.x - __bfloat162float(h0));
    __nv_bfloat16 l1 = __float2bfloat16(v.y - __bfloat162float(h1));
    __nv_bfloat16 l2 = __float2bfloat16(v.z - __bfloat162float(h2));
    __nv_bfloat16 l3 = __float2bfloat16(v.w - __bfloat162float(h3));
    __nv_bfloat162* hi2 = (__nv_bfloat162*)hi;
    __nv_bfloat162* lo2 = (__nv_bfloat162*)lo;
    hi2[2 * i]     = __nv_bfloat162(h0, h1);
    hi2[2 * i + 1] = __nv_bfloat162(h2, h3);
    lo2[2 * i]     = __nv_bfloat162(l0, l1);
    lo2[2 * i + 1] = __nv_bfloat162(l2, l3);
}

// ---------------------------------------------------------------------------
// mma.sync split-bf16 SGEMM (unchanged from R3 — passed).
// ---------------------------------------------------------------------------
#define TCT16 16384u
#define TC_SMEM_BYTES (2u * 4u * TCT16)

__global__ void __launch_bounds__(256, 1)
sgemm_tc(const __nv_bfloat16* __restrict__ Ahi, const __nv_bfloat16* __restrict__ Alo,
         const __nv_bfloat16* __restrict__ Bhi, const __nv_bfloat16* __restrict__ Blo,
         float* __restrict__ C, int head_layout)
{
    extern __shared__ char smem[];
    const uint32_t sbase = smem_u32(smem);

    const int tid  = threadIdx.x;
    const int lane = tid & 31;
    const int w    = tid >> 5;
    const int wm   = w >> 2;
    const int wn   = w & 3;
    const int m0w  = wm * 64;
    const int n0w  = wn * 32;

    const int bx = blockIdx.x;
    const int by = blockIdx.y;
    const int m0 = by * 128;
    const int n0 = bx * 128;

    uint32_t swofs[4];
#pragma unroll
    for (int t = 0; t < 4; t++) {
        const int u = tid + (t << 8);
        swofs[t] = swz128((uint32_t)((u >> 3) * 128 + (u & 7) * 16));
    }

    float acc[4][4][4];
#pragma unroll
    for (int i = 0; i < 4; i++)
#pragma unroll
        for (int j = 0; j < 4; j++)
#pragma unroll
            for (int r = 0; r < 4; r++) acc[i][j][r] = 0.0f;

    const uint32_t arow = (uint32_t)(m0w + (lane & 15));
    const uint32_t acol = (uint32_t)((lane >> 4) << 4);
    const uint32_t brow = (uint32_t)(n0w + (lane & 7));
    const uint32_t bcol = (uint32_t)(((lane >> 3) & 1) << 4);

#define LOAD_CHUNK(c, buf)                                                     \
    {                                                                          \
        const uint32_t bofs = sbase + (uint32_t)(buf) * (4u * TCT16);          \
        const int k0 = (c) * 64;                                               \
        _Pragma("unroll")                                                      \
        for (int t = 0; t < 4; t++) {                                          \
            const int u = tid + (t << 8);                                      \
            const int r = u >> 3;                                              \
            const int c16 = u & 7;                                             \
            const size_t ga = (size_t)(m0 + r) * D_ + k0 + c16 * 8;            \
            const size_t gb = (size_t)(n0 + r) * D_ + k0 + c16 * 8;            \
            cp16(bofs + 0u * TCT16 + swofs[t], Ahi + ga);                      \
            cp16(bofs + 1u * TCT16 + swofs[t], Alo + ga);                      \
            cp16(bofs + 2u * TCT16 + swofs[t], Bhi + gb);                      \
            cp16(bofs + 3u * TCT16 + swofs[t], Blo + gb);                      \
        }                                                                      \
        CP_COMMIT();                                                           \
    }

    LOAD_CHUNK(0, 0);

    for (int c = 0; c < 32; c++) {
        if (c < 31) {
            LOAD_CHUNK(c + 1, (c + 1) & 1);
            asm volatile("cp.async.wait_group 1;" ::: "memory");
        } else {
            asm volatile("cp.async.wait_group 0;" ::: "memory");
        }
        __syncthreads();

        const uint32_t bofs = sbase + (uint32_t)(c & 1) * (4u * TCT16);
        const uint32_t Abase_hi = bofs + 0u * TCT16;
        const uint32_t Abase_lo = bofs + 1u * TCT16;
        const uint32_t Bbase_hi = bofs + 2u * TCT16;
        const uint32_t Bbase_lo = bofs + 3u * TCT16;

#pragma unroll
        for (int kk = 0; kk < 4; kk++) {
            uint32_t ah[4][4], al[4][4], bh[4][2], bl[4][2];
            const uint32_t kb = (uint32_t)(kk * 32);
#pragma unroll
            for (int mt = 0; mt < 4; mt++) {
                const uint32_t ofs = swz128((arow + mt * 16u) * 128u + acol + kb);
                ldsm_x4(Abase_hi + ofs, ah[mt]);
                ldsm_x4(Abase_lo + ofs, al[mt]);
            }
#pragma unroll
            for (int nt = 0; nt < 4; nt++) {
                const uint32_t ofs = swz128((brow + nt * 8u) * 128u + bcol + kb);
                ldsm_x2(Bbase_hi + ofs, bh[nt]);
                ldsm_x2(Bbase_lo + ofs, bl[nt]);
            }
#pragma unroll
            for (int mt = 0; mt < 4; mt++)
#pragma unroll
                for (int nt = 0; nt < 4; nt++) {
                    mma16816(acc[mt][nt], ah[mt], bh[nt]);
                    mma16816(acc[mt][nt], ah[mt], bl[nt]);
                    mma16816(acc[mt][nt], al[mt], bh[nt]);
                }
        }
        __syncthreads();
    }

    const int lr = lane >> 2;
    const int lc = (lane & 3) * 2;
#pragma unroll
    for (int mt = 0; mt < 4; mt++) {
#pragma unroll
        for (int rr = 0; rr < 2; rr++) {
            const int m = m0 + m0w + mt * 16 + rr * 8 + lr;
            if (head_layout) {
                const int bb = m >> 11, s = m & (S_ - 1);
                const size_t rowoff = ((size_t)(bb * H_) * S_ + s) * HD_;
#pragma unroll
                for (int nt = 0; nt < 4; nt++) {
                    const int n = n0 + n0w + nt * 8 + lc;
                    const int h = n >> 7, hd = n & 127;
                    float2 v = rr == 0
                        ? make_float2(acc[mt][nt][0], acc[mt][nt][1])
                        : make_float2(acc[mt][nt][2], acc[mt][nt][3]);
                    *(float2*)&C[rowoff + (size_t)h * S_ * HD_ + hd] = v;
                }
            } else {
                const size_t dstbase = (size_t)m * D_;
#pragma unroll
                for (int nt = 0; nt < 4; nt++) {
                    const int n = n0 + n0w + nt * 8 + lc;
                    float2 v = rr == 0
                        ? make_float2(acc[mt][nt][0], acc[mt][nt][1])
                        : make_float2(acc[mt][nt][2], acc[mt][nt][3]);
                    *(float2*)&C[dstbase + n] = v;
                }
            }
        }
    }
}

// ---------------------------------------------------------------------------
// RoPE tables + rope-apply that emits bf16 hi/lo (Q pre-scaled by 1/sqrt(HD))
// ---------------------------------------------------------------------------
__global__ void rope_table_kernel()
{
    int idx = blockIdx.x * blockDim.x + threadIdx.x;
    if (idx >= S_ * 64) return;
    const int i = idx & 63;
    const int s = idx >> 6;
    const float inv_freq = (float)pow(10000.0, -(double)i * (1.0 / 64.0));
    const double ang = (double)s * (double)inv_freq;
    double sd, cd;
    sincos(ang, &sd, &cd);
    g_cos[idx] = (float)cd;
    g_sin[idx] = (float)sd;
}

__device__ __forceinline__ void split1(float x, __nv_bfloat16& h, __nv_bfloat16& l) {
    h = __float2bfloat16(x);
    l = __float2bfloat16(x - __bfloat162float(h));
}

__global__ void rope_split_kernel(const float* __restrict__ Q,
                                  const float* __restrict__ K, int total)
{
    int idx = blockIdx.x * blockDim.x + threadIdx.x;
    if (idx >= total) return;                  // total = B*H*S*64
    const int i  = idx & 63;
    const int s  = (idx >> 6) & (S_ - 1);
    const int bh = idx >> 17;

    const int ti = (s << 6) + i;
    const float c  = g_cos[ti];
    const float sn = g_sin[ti];
    const float sc = 0.08838834764831845f;    // 1/sqrt(128)

    const size_t base = ((size_t)bh * S_ + s) * HD_ + i;
    float q1 = Q[base], q2 = Q[base + 64];
    float r1 = (q1 * c - q2 * sn) * sc;
    float r2 = (q1 * sn + q2 * c) * sc;
    __nv_bfloat16 h, l;
    split1(r1, h, l); g_qh[base] = h;      g_ql[base] = l;
    split1(r2, h, l); g_qh[base + 64] = h; g_ql[base + 64] = l;

    float k1 = K[base], k2 = K[base + 64];
    float t1 = k1 * c - k2 * sn;
    float t2 = k1 * sn + k2 * c;
    split1(t1, h, l); g_kh[base] = h;      g_kl[base] = l;
    split1(t2, h, l); g_kh[base + 64] = h; g_kl[base + 64] = l;
}

// ---------------------------------------------------------------------------
// Tensor-core flash attention (causal), split-bf16 everywhere.
// CTA: 128 q-rows, 8 warps x 16 rows; iterates 64-col K/V tiles.
// smem: Qhi/Qlo 32KB each; double-buffered {Khi,Klo,Vhi,Vlo} 16KB each.
// ---------------------------------------------------------------------------
#define FL_SMEM (65536 + 2 * 65536)

__global__ void __launch_bounds__(256, 1)
flash_tc(const __nv_bfloat16* __restrict__ Qhi, const __nv_bfloat16* __restrict__ Qlo,
         const __nv_bfloat16* __restrict__ Khi, const __nv_bfloat16* __restrict__ Klo,
         const __nv_bfloat16* __restrict__ Vhi, const __nv_bfloat16* __restrict__ Vlo,
         float* __restrict__ AO)
{
    extern __shared__ char smem[];
    const uint32_t sb = smem_u32(smem);
    const uint32_t sQh = sb;
    const uint32_t sQl = sb + 32768u;

    const int tid  = threadIdx.x;
    const int lane = tid & 31;
    const int w    = tid >> 5;
    const int lr   = lane >> 2;
    const int lc2  = (lane & 3) * 2;

    const int qt = (int)gridDim.x - 1 - (int)blockIdx.x;   // heavy CTAs first
    const int h  = blockIdx.y;
    const int b  = blockIdx.z;
    const size_t bh = ((size_t)(b * H_ + h)) * S_ * HD_;

    const __nv_bfloat16* Qhg = Qhi + bh + (size_t)qt * 128 * HD_;
    const __nv_bfloat16* Qlg = Qlo + bh + (size_t)qt * 128 * HD_;

    // ---- load Q (hi/lo) ----
    for (int i = tid; i < 2048; i += 256) {
        const uint32_t r = (uint32_t)(i >> 4);
        const uint32_t cb = (uint32_t)((i & 15) << 4);
        const uint32_t so = swzf(r, cb);
        cp16(sQh + so, Qhg + (size_t)r * HD_ + (i & 15) * 8);
        cp16(sQl + so, Qlg + (size_t)r * HD_ + (i & 15) * 8);
    }

#define LOAD_KV(jj, buf)                                                       \
    {                                                                          \
        const uint32_t kvb = sb + 65536u + (uint32_t)(buf) * 65536u;           \
        const size_t rg0 = (size_t)(jj) * 64;                                  \
        for (int i = tid; i < 1024; i += 256) {                                \
            const uint32_t r = (uint32_t)(i >> 4);                             \
            const uint32_t cb = (uint32_t)((i & 15) << 4);                     \
            const uint32_t so = swzf(r, cb);                                   \
            const size_t g = bh + (rg0 + r) * HD_ + (i & 15) * 8;              \
            cp16(kvb + so, Khi + g);                                           \
            cp16(kvb + 16384u + so, Klo + g);                                  \
            cp16(kvb + 32768u + so, Vhi + g);                                  \
            cp16(kvb + 49152u + so, Vlo + g);                                  \
        }                                                                      \
    }

    LOAD_KV(0, 0);
    CP_COMMIT();

    float o[16][4];
#pragma unroll
    for (int i = 0; i < 16; i++)
#pragma unroll
        for (int e = 0; e < 4; e++) o[i][e] = 0.0f;
    float m0 = -1e30f, m1 = -1e30f, l0 = 0.0f, l1 = 0.0f;

    const int jmax = 2 * qt + 1;
    const int rbase = qt * 128 + w * 16 + lr;

    for (int j = 0; j <= jmax; j++) {
        if (j < jmax) {
            LOAD_KV(j + 1, (j + 1) & 1);
            CP_COMMIT();
            asm volatile("cp.async.wait_group 1;" ::: "memory");
        } else {
            asm volatile("cp.async.wait_group 0;" ::: "memory");
        }
        __syncthreads();

        const uint32_t kvb = sb + 65536u + (uint32_t)(j & 1) * 65536u;
        const uint32_t sKh = kvb;
        const uint32_t sKl = kvb + 16384u;
        const uint32_t sVh = kvb + 32768u;
        const uint32_t sVl = kvb + 49152u;

        // ---- S = Q K^T (3-product) ----
        float sacc[8][4];
#pragma unroll
        for (int nt = 0; nt < 8; nt++)
#pragma unroll
            for (int e = 0; e < 4; e++) sacc[nt][e] = 0.0f;

#pragma unroll
        for (int kc = 0; kc < 8; kc++) {
            const uint32_t ao_ = swzf((uint32_t)(w * 16 + (lane & 15)),
                                      (uint32_t)(kc * 32 + ((lane >> 4) << 4)));
            uint32_t ah[4], al[4];
            ldsm_x4(sQh + ao_, ah);
            ldsm_x4(sQl + ao_, al);
#pragma unroll
            for (int nt = 0; nt < 8; nt++) {
                const uint32_t bo = swzf((uint32_t)(nt * 8 + (lane & 7)),
                                         (uint32_t)(kc * 32 + (((lane >> 3) & 1) << 4)));
                uint32_t bhf[2], blf[2];
                ldsm_x2(sKh + bo, bhf);
                ldsm_x2(sKl + bo, blf);
                mma16816(sacc[nt], ah, bhf);
                mma16816(sacc[nt], ah, blf);
                mma16816(sacc[nt], al, bhf);
            }
        }

        // ---- causal mask (only partial tiles) ----
        if (j >= 2 * qt) {
            const int cb0 = j * 64 + lc2;
#pragma unroll
            for (int nt = 0; nt < 8; nt++)
#pragma unroll
                for (int e = 0; e < 4; e++) {
                    const int col = cb0 + nt * 8 + (e & 1);
                    const int row = rbase + 8 * (e >> 1);
                    if (col > row) sacc[nt][e] = -1e30f;
                }
        }

        // ---- online softmax ----
        float mx0 = -1e30f, mx1 = -1e30f;
#pragma unroll
        for (int nt = 0; nt < 8; nt++) {
            mx0 = fmaxf(mx0, fmaxf(sacc[nt][0], sacc[nt][1]));
            mx1 = fmaxf(mx1, fmaxf(sacc[nt][2], sacc[nt][3]));
        }
        mx0 = fmaxf(mx0, __shfl_xor_sync(0xffffffffu, mx0, 1));
        mx0 = fmaxf(mx0, __shfl_xor_sync(0xffffffffu, mx0, 2));
        mx1 = fmaxf(mx1, __shfl_xor_sync(0xffffffffu, mx1, 1));
        mx1 = fmaxf(mx1, __shfl_xor_sync(0xffffffffu, mx1, 2));

        const float mn0 = fmaxf(m0, mx0);
        const float mn1 = fmaxf(m1, mx1);
        const float al0 = __expf(m0 - mn0);
        const float al1 = __expf(m1 - mn1);
        m0 = mn0; m1 = mn1;

        float s0 = 0.0f, s1 = 0.0f;
#pragma unroll
        for (int nt = 0; nt < 8; nt++) {
            sacc[nt][0] = __expf(sacc[nt][0] - mn0); s0 += sacc[nt][0];
            sacc[nt][1] = __expf(sacc[nt][1] - mn0); s0 += sacc[nt][1];
            sacc[nt][2] = __expf(sacc[nt][2] - mn1); s1 += sacc[nt][2];
            sacc[nt][3] = __expf(sacc[nt][3] - mn1); s1 += sacc[nt][3];
        }
        s0 += __shfl_xor_sync(0xffffffffu, s0, 1);
        s0 += __shfl_xor_sync(0xffffffffu, s0, 2);
        s1 += __shfl_xor_sync(0xffffffffu, s1, 1);
        s1 += __shfl_xor_sync(0xffffffffu, s1, 2);
        l0 = l0 * al0 + s0;
        l1 = l1 * al1 + s1;

#pragma unroll
        for (int dt = 0; dt < 16; dt++) {
            o[dt][0] *= al0; o[dt][1] *= al0;
            o[dt][2] *= al1; o[dt][3] *= al1;
        }

        // ---- O += P V (P split in registers, 3-product) ----
#pragma unroll
        for (int t = 0; t < 4; t++) {
            uint32_t ph[4], pl[4];
#pragma unroll
            for (int q2 = 0; q2 < 2; q2++)
#pragma unroll
                for (int rr = 0; rr < 2; rr++) {
                    const float x = sacc[2 * t + q2][2 * rr];
                    const float y = sacc[2 * t + q2][2 * rr + 1];
                    __nv_bfloat16 bx = __float2bfloat16(x);
                    __nv_bfloat16 by = __float2bfloat16(y);
                    __nv_bfloat16 cx = __float2bfloat16(x - __bfloat162float(bx));
                    __nv_bfloat16 cy = __float2bfloat16(y - __bfloat162float(by));
                    ph[q2 * 2 + rr] = pack2(bx, by);
                    pl[q2 * 2 + rr] = pack2(cx, cy);
                }
#pragma unroll
            for (int dt = 0; dt < 16; dt++) {
                const uint32_t bo = swzf((uint32_t)(t * 16 + (lane & 15)),
                                         (uint32_t)(dt * 16));
                uint32_t bvh[2], bvl[2];
                ldsm_x2t(sVh + bo, bvh);
                ldsm_x2t(sVl + bo, bvl);
                mma16816(o[dt], ph, bvh);
                mma16816(o[dt], ph, bvl);
                mma16816(o[dt], pl, bvh);
            }
        }
        __syncthreads();
    }

    // ---- epilogue ----
    const float inv0 = 1.0f / l0;
    const float inv1 = 1.0f / l1;
    const int srow0 = qt * 128 + w * 16 + lr;
    const size_t d0 = ((size_t)(b * S_ + srow0)) * D_ + h * HD_;
    const size_t d1 = ((size_t)(b * S_ + srow0 + 8)) * D_ + h * HD_;
#pragma unroll
    for (int dt = 0; dt < 16; dt++) {
        *(float2*)&AO[d0 + dt * 8 + lc2] = make_float2(o[dt][0] * inv0, o[dt][1] * inv0);
        *(float2*)&AO[d1 + dt * 8 + lc2] = make_float2(o[dt][2] * inv1, o[dt][3] * inv1);
    }
}

// ---------------------------------------------------------------------------
extern "C" void kernel_launch(void* const* d_in, const int* in_sizes, int n_in,
                              void* d_out, int out_size)
{
    (void)in_sizes; (void)n_in; (void)out_size;
    const float* x  = (const float*)d_in[0];
    const float* Wq = (const float*)d_in[2];
    const float* Wk = (const float*)d_in[3];
    const float* Wv = (const float*)d_in[4];
    const float* Wo = (const float*)d_in[5];
    float* out = (float*)d_out;

    float *q, *k, *v, *ao;
    cudaGetSymbolAddress((void**)&q,  g_Q);
    cudaGetSymbolAddress((void**)&k,  g_K);
    cudaGetSymbolAddress((void**)&v,  g_V);
    cudaGetSymbolAddress((void**)&ao, g_AO);

    __nv_bfloat16 *xhi, *xlo, *aohi, *aolo;
    __nv_bfloat16 *wqhi, *wqlo, *wkhi, *wklo, *wvhi, *wvlo, *wohi, *wolo;
    __nv_bfloat16 *qh, *ql, *kh, *kl, *vh, *vl;
    cudaGetSymbolAddress((void**)&xhi, g_xhi);
    cudaGetSymbolAddress((void**)&xlo, g_xlo);
    cudaGetSymbolAddress((void**)&aohi, g_aohi);
    cudaGetSymbolAddress((void**)&aolo, g_aolo);
    cudaGetSymbolAddress((void**)&wqhi, g_wqhi);
    cudaGetSymbolAddress((void**)&wqlo, g_wqlo);
    cudaGetSymbolAddress((void**)&wkhi, g_wkhi);
    cudaGetSymbolAddress((void**)&wklo, g_wklo);
    cudaGetSymbolAddress((void**)&wvhi, g_wvhi);
    cudaGetSymbolAddress((void**)&wvlo, g_wvlo);
    cudaGetSymbolAddress((void**)&wohi, g_wohi);
    cudaGetSymbolAddress((void**)&wolo, g_wolo);
    cudaGetSymbolAddress((void**)&qh, g_qh);
    cudaGetSymbolAddress((void**)&ql, g_ql);
    cudaGetSymbolAddress((void**)&kh, g_kh);
    cudaGetSymbolAddress((void**)&kl, g_kl);
    cudaGetSymbolAddress((void**)&vh, g_vh);
    cudaGetSymbolAddress((void**)&vl, g_vl);

    cudaFuncSetAttribute(sgemm_tc,
                         cudaFuncAttributeMaxDynamicSharedMemorySize, TC_SMEM_BYTES);
    cudaFuncSetAttribute(flash_tc,
                         cudaFuncAttributeMaxDynamicSharedMemorySize, FL_SMEM);

    // 1) splits of inputs
    const int xn4 = (B_ * S_ * D_) / 4;
    const int wn4 = (D_ * D_) / 4;
    split_bf16<<<(xn4 + 255) / 256, 256>>>(x, xhi, xlo, xn4);
    split_bf16<<<(wn4 + 255) / 256, 256>>>(Wq, wqhi, wqlo, wn4);
    split_bf16<<<(wn4 + 255) / 256, 256>>>(Wk, wkhi, wklo, wn4);
    split_bf16<<<(wn4 + 255) / 256, 256>>>(Wv, wvhi, wvlo, wn4);
    split_bf16<<<(wn4 + 255) / 256, 256>>>(Wo, wohi, wolo, wn4);

    // 2) rope tables
    rope_table_kernel<<<(S_ * 64 + 255) / 256, 256>>>();

    // 3) projections (tensor cores)
    dim3 ggrid(D_ / 128, (B_ * S_) / 128);
    sgemm_tc<<<ggrid, 256, TC_SMEM_BYTES>>>(xhi, xlo, wqhi, wqlo, q, 1);
    sgemm_tc<<<ggrid, 256, TC_SMEM_BYTES>>>(xhi, xlo, wkhi, wklo, k, 1);
    sgemm_tc<<<ggrid, 256, TC_SMEM_BYTES>>>(xhi, xlo, wvhi, wvlo, v, 1);

    // 4) rope + split Q/K to bf16 hi/lo; split V
    const int rope_total = B_ * H_ * S_ * 64;
    rope_split_kernel<<<(rope_total + 255) / 256, 256>>>(q, k, rope_total);
    const int vn4 = (B_ * H_ * S_ * HD_) / 4;
    split_bf16<<<(vn4 + 255) / 256, 256>>>(v, vh, vl, vn4);

    // 5) tensor-core flash attention
    flash_tc<<<dim3(S_ / 128, H_, B_), 256, FL_SMEM>>>(qh, ql, kh, kl, vh, vl, ao);

    // 6) output projection
    split_bf16<<<(xn4 + 255) / 256, 256>>>(ao, aohi, aolo, xn4);
    sgemm_tc<<<ggrid, 256, TC_SMEM_BYTES>>>(aohi, aolo, wohi, wolo, out, 0);
}